// round 4
// baseline (speedup 1.0000x reference)
#include <cuda_runtime.h>
#include <cuda_bf16.h>
#include <cstdint>

#define B_ 4
#define T_ 2048
#define H_ 2048
#define F_ 8192
#define M_ (B_*T_)   // 8192 tokens

// ---------------- device scratch (static; no allocations) ----------------
__device__ signed char g_wkq[(size_t)F_*H_];   // ternary key weight codes
__device__ signed char g_wrq[(size_t)H_*H_];   // ternary receptance weight codes
__device__ signed char g_wvq[(size_t)H_*F_];   // ternary value weight codes
__device__ signed char g_aK[(size_t)M_*H_];    // int8 codes of key_in
__device__ signed char g_aR[(size_t)M_*H_];    // int8 codes of rec_in
__device__ signed char g_aV[(size_t)M_*F_];    // int8 codes of k
__device__ float g_kraw[(size_t)M_*F_];        // k = relu(.)^2, fp32
__device__ float g_rbuf[(size_t)M_*H_];        // sigmoid(receptance)
__device__ float g_sK[M_], g_sR[M_], g_sV[M_]; // per-row dequant scale
__device__ float g_part[3*1024];
__device__ float g_ws[6];                      // [2i]=ws, [2i+1]=1/ws

// ---------------- reductions ----------------
__device__ __forceinline__ float warpSum(float v){
  #pragma unroll
  for(int o=16;o;o>>=1) v += __shfl_xor_sync(0xffffffffu, v, o);
  return v;
}
__device__ __forceinline__ float warpMax(float v){
  #pragma unroll
  for(int o=16;o;o>>=1) v = fmaxf(v, __shfl_xor_sync(0xffffffffu, v, o));
  return v;
}
__device__ __forceinline__ float blkSum(float v, float* sm){
  int t = threadIdx.x, nw = blockDim.x >> 5;
  v = warpSum(v);
  if((t&31)==0) sm[t>>5] = v;
  __syncthreads();
  float r = (t < nw) ? sm[t] : 0.f;
  r = warpSum(r);
  if(t==0) sm[0] = r;
  __syncthreads();
  r = sm[0];
  __syncthreads();
  return r;
}
__device__ __forceinline__ float blkMax(float v, float* sm){
  int t = threadIdx.x, nw = blockDim.x >> 5;
  v = warpMax(v);
  if((t&31)==0) sm[t>>5] = v;
  __syncthreads();
  float r = (t < nw) ? sm[t] : 0.f;
  r = warpMax(r);
  if(t==0) sm[0] = r;
  __syncthreads();
  r = sm[0];
  __syncthreads();
  return r;
}

// ---------------- weight scale: two-stage deterministic mean(|w|) ----------------
__global__ void k_absum(const float* __restrict__ w, int n4, int poff){
  __shared__ float sm[32];
  float s = 0.f;
  const float4* w4 = (const float4*)w;
  for(int i = blockIdx.x*blockDim.x + threadIdx.x; i < n4; i += gridDim.x*blockDim.x){
    float4 v = w4[i];
    s += fabsf(v.x) + fabsf(v.y) + fabsf(v.z) + fabsf(v.w);
  }
  s = blkSum(s, sm);
  if(threadIdx.x == 0) g_part[poff + blockIdx.x] = s;
}

__global__ void k_wsfin(){
  __shared__ float sm[32];
  const float cnts[3] = {(float)((size_t)F_*H_), (float)((size_t)H_*H_), (float)((size_t)H_*F_)};
  for(int i=0;i<3;i++){
    float v = g_part[i*1024 + threadIdx.x];
    float tot = blkSum(v, sm);
    if(threadIdx.x == 0){
      float mean = tot / cnts[i];
      float c = fmaxf(mean, 1e-5f);
      g_ws[2*i]   = 1.f/c;
      g_ws[2*i+1] = c;
    }
    __syncthreads();
  }
}

// ---------------- ternary weight quantization (int8 out) ----------------
__global__ void k_quantw(const float* __restrict__ w, signed char* __restrict__ wq,
                         int n4, int wsidx){
  float ws = g_ws[2*wsidx];
  for(int i = blockIdx.x*blockDim.x + threadIdx.x; i < n4; i += gridDim.x*blockDim.x){
    float4 v = ((const float4*)w)[i];
    int q0 = (int)fminf(fmaxf(rintf(v.x*ws), -1.f), 1.f);
    int q1 = (int)fminf(fmaxf(rintf(v.y*ws), -1.f), 1.f);
    int q2 = (int)fminf(fmaxf(rintf(v.z*ws), -1.f), 1.f);
    int q3 = (int)fminf(fmaxf(rintf(v.w*ws), -1.f), 1.f);
    uint32_t p = (uint32_t)(q0&0xff) | ((uint32_t)(q1&0xff)<<8) |
                 ((uint32_t)(q2&0xff)<<16) | ((uint32_t)(q3&0xff)<<24);
    ((uint32_t*)wq)[i] = p;
  }
}

// ---------------- token shift + RMSNorm + int8 activation quant ----------------
__global__ void k_actprep(const float* __restrict__ hidden,
                          const float* __restrict__ tmk, const float* __restrict__ tmr,
                          const float* __restrict__ nk,  const float* __restrict__ nr){
  __shared__ float sm[32];
  int m = blockIdx.x;
  int t = m & (T_-1);
  const float4* cur = (const float4*)(hidden + (size_t)m*H_);
  const float4* tmk4 = (const float4*)tmk;
  const float4* tmr4 = (const float4*)tmr;
  const float4* nk4  = (const float4*)nk;
  const float4* nr4  = (const float4*)nr;
  int base = threadIdx.x*2;              // 2 float4 per thread = 8 elems
  float kin[8], rin[8], wk[8], wr[8];
  float ssk=0.f, ssr=0.f, amk=0.f, amr=0.f;
  #pragma unroll
  for(int j=0;j<2;j++){
    float4 xc = cur[base+j];
    float4 xp = (t==0) ? make_float4(0.f,0.f,0.f,0.f) : cur[base+j - H_/4];
    float4 a = tmk4[base+j], b = tmr4[base+j];
    float4 wkv = nk4[base+j], wrv = nr4[base+j];
    float* kc = kin + 4*j; float* rc = rin + 4*j;
    float* wkc = wk + 4*j; float* wrc = wr + 4*j;
    kc[0] = xc.x*a.x + xp.x*(1.f-a.x); kc[1] = xc.y*a.y + xp.y*(1.f-a.y);
    kc[2] = xc.z*a.z + xp.z*(1.f-a.z); kc[3] = xc.w*a.w + xp.w*(1.f-a.w);
    rc[0] = xc.x*b.x + xp.x*(1.f-b.x); rc[1] = xc.y*b.y + xp.y*(1.f-b.y);
    rc[2] = xc.z*b.z + xp.z*(1.f-b.z); rc[3] = xc.w*b.w + xp.w*(1.f-b.w);
    wkc[0]=wkv.x; wkc[1]=wkv.y; wkc[2]=wkv.z; wkc[3]=wkv.w;
    wrc[0]=wrv.x; wrc[1]=wrv.y; wrc[2]=wrv.z; wrc[3]=wrv.w;
    #pragma unroll
    for(int u=0;u<4;u++){
      ssk += kc[u]*kc[u]; ssr += rc[u]*rc[u];
      amk = fmaxf(amk, fabsf(kc[u]*wkc[u]));
      amr = fmaxf(amr, fabsf(rc[u]*wrc[u]));
    }
  }
  float tssk = blkSum(ssk, sm);
  float tssr = blkSum(ssr, sm);
  float tamk = blkMax(amk, sm);
  float tamr = blkMax(amr, sm);
  float rk = rsqrtf(tssk*(1.f/H_) + 1e-8f);
  float rr = rsqrtf(tssr*(1.f/H_) + 1e-8f);
  float rsK = fmaxf(tamk*rk, 1e-5f);
  float rsR = fmaxf(tamr*rr, 1e-5f);
  float sk = 127.f/rsK, sr = 127.f/rsR;
  uint32_t pk[2], pr[2];
  #pragma unroll
  for(int w2=0; w2<2; w2++){
    uint32_t vk=0, vr=0;
    #pragma unroll
    for(int u=0;u<4;u++){
      int idx = 4*w2+u;
      int qk = (int)fminf(fmaxf(rintf(kin[idx]*wk[idx]*rk*sk), -128.f), 127.f);
      int qr = (int)fminf(fmaxf(rintf(rin[idx]*wr[idx]*rr*sr), -128.f), 127.f);
      vk |= (uint32_t)(qk&0xff) << (8*u);
      vr |= (uint32_t)(qr&0xff) << (8*u);
    }
    pk[w2]=vk; pr[w2]=vr;
  }
  uint2* ok = (uint2*)(g_aK + (size_t)m*H_) + threadIdx.x;
  uint2* orr = (uint2*)(g_aR + (size_t)m*H_) + threadIdx.x;
  *ok = make_uint2(pk[0], pk[1]);
  *orr = make_uint2(pr[0], pr[1]);
  if(threadIdx.x == 0){ g_sK[m] = rsK*(1.f/127.f); g_sR[m] = rsR*(1.f/127.f); }
}

// ---------------- RMSNorm + int8 quant of k rows (F=8192) ----------------
__global__ void k_quantK(const float* __restrict__ nvw){
  __shared__ float sm[32];
  int m = blockIdx.x;
  const float4* row = (const float4*)(g_kraw + (size_t)m*F_);
  const float4* nv4 = (const float4*)nvw;
  int base = threadIdx.x*8;              // 8 float4 per thread = 32 elems
  float v[32], nw[32];
  float ss=0.f, am=0.f;
  #pragma unroll
  for(int j=0;j<8;j++){
    float4 x = row[base+j];
    float4 n = nv4[base+j];
    v[4*j+0]=x.x; v[4*j+1]=x.y; v[4*j+2]=x.z; v[4*j+3]=x.w;
    nw[4*j+0]=n.x; nw[4*j+1]=n.y; nw[4*j+2]=n.z; nw[4*j+3]=n.w;
    ss += x.x*x.x + x.y*x.y + x.z*x.z + x.w*x.w;
    am = fmaxf(am, fmaxf(fmaxf(fabsf(x.x*n.x), fabsf(x.y*n.y)),
                         fmaxf(fabsf(x.z*n.z), fabsf(x.w*n.w))));
  }
  float tss = blkSum(ss, sm);
  float tam = blkMax(am, sm);
  float rinv = rsqrtf(tss*(1.f/F_) + 1e-8f);
  float rs = fmaxf(tam*rinv, 1e-5f);
  float s = 127.f/rs;
  uint32_t pk[8];
  #pragma unroll
  for(int w4=0; w4<8; w4++){
    uint32_t p=0;
    #pragma unroll
    for(int u=0;u<4;u++){
      int idx = 4*w4+u;
      int q = (int)fminf(fmaxf(rintf(v[idx]*nw[idx]*rinv*s), -128.f), 127.f);
      p |= (uint32_t)(q&0xff) << (8*u);
    }
    pk[w4]=p;
  }
  uint4* o = (uint4*)(g_aV + (size_t)m*F_) + threadIdx.x*2;
  o[0] = make_uint4(pk[0],pk[1],pk[2],pk[3]);
  o[1] = make_uint4(pk[4],pk[5],pk[6],pk[7]);
  if(threadIdx.x == 0) g_sV[m] = rs*(1.f/127.f);
}

// ============ int8 tensor-core GEMM: C[M,N] = A[M,K] * Bw[N,K]^T ============
#define BM 128
#define BN 128
#define BKg 64          // 64 int8 = 64 B per row
#define LDT 80          // 64 + 16 pad bytes: frag LDS conflict-free (banks (20g+q)%32)
#define NSTAGE 3
#define STAGE_B ((BM+BN)*LDT)   // 20480 B

__device__ __forceinline__ void cp16(uint32_t s, const void* g){
  asm volatile("cp.async.cg.shared.global [%0], [%1], 16;" :: "r"(s), "l"(g));
}
__device__ __forceinline__ void cp_commit(){ asm volatile("cp.async.commit_group;" ::: "memory"); }
template<int N> __device__ __forceinline__ void cp_wait(){
  asm volatile("cp.async.wait_group %0;" :: "n"(N) : "memory");
}
__device__ __forceinline__ void imma16832(int* c, const uint32_t* a, const uint32_t* b){
  asm volatile(
    "mma.sync.aligned.m16n8k32.row.col.s32.s8.s8.s32 "
    "{%0,%1,%2,%3}, {%4,%5,%6,%7}, {%8,%9}, {%0,%1,%2,%3};\n"
    : "+r"(c[0]), "+r"(c[1]), "+r"(c[2]), "+r"(c[3])
    : "r"(a[0]), "r"(a[1]), "r"(a[2]), "r"(a[3]), "r"(b[0]), "r"(b[1]));
}

// MODE 0: key   -> g_kraw = relu(x)^2
// MODE 1: rec   -> g_rbuf = sigmoid(x)
// MODE 2: value -> Cout   = x * g_rbuf
template<int MODE>
__global__ __launch_bounds__(256) void k_gemm(float* __restrict__ Cout){
  constexpr int Ndim = (MODE==0) ? F_ : H_;
  constexpr int Kdim = (MODE==2) ? F_ : H_;
  constexpr int NKT  = Kdim / BKg;

  const signed char* __restrict__ A  = (MODE==0) ? g_aK  : (MODE==1) ? g_aR  : g_aV;
  const signed char* __restrict__ Bw = (MODE==0) ? g_wkq : (MODE==1) ? g_wrq : g_wvq;
  const float* __restrict__ rowscale = (MODE==0) ? g_sK  : (MODE==1) ? g_sR  : g_sV;
  float* __restrict__ C              = (MODE==0) ? g_kraw : (MODE==1) ? g_rbuf : Cout;
  const float wdeq = g_ws[2*((MODE==0)?0:(MODE==1)?1:2) + 1];

  extern __shared__ __align__(128) signed char smem[];  // NSTAGE stages

  const int tid = threadIdx.x;
  const int bm = blockIdx.y*BM, bn = blockIdx.x*BN;

  auto loads = [&](int buf, int kt){
    signed char* st = smem + buf*STAGE_B;
    const signed char* Ak = A  + (size_t)bm*Kdim + kt*BKg;
    const signed char* Bk = Bw + (size_t)bn*Kdim + kt*BKg;
    #pragma unroll
    for(int i=0;i<4;i++){
      int chunk = tid + 256*i;         // 0..1023 : 256 rows x 4 x 16B
      int row = chunk >> 2;
      int kc  = (chunk & 3) << 4;      // 0,16,32,48 bytes
      const signed char* gp = (row < BM) ? (Ak + (size_t)row*Kdim + kc)
                                         : (Bk + (size_t)(row-BM)*Kdim + kc);
      cp16((uint32_t)__cvta_generic_to_shared(st + row*LDT + kc), gp);
    }
    cp_commit();
  };

  const int warp = tid >> 5, lane = tid & 31;
  const int wm = (warp >> 2) * 64;   // 2 warps in M
  const int wn = (warp & 3) * 32;    // 4 warps in N
  const int g = lane >> 2, q = lane & 3;

  int acc[4][4][4];
  #pragma unroll
  for(int a0=0;a0<4;a0++)
    #pragma unroll
    for(int b0=0;b0<4;b0++)
      #pragma unroll
      for(int c0=0;c0<4;c0++) acc[a0][b0][c0]=0;

  #pragma unroll
  for(int s=0;s<NSTAGE;s++) loads(s, s);

  #pragma unroll 1
  for(int kt=0; kt<NKT; kt++){
    cp_wait<NSTAGE-1>();
    __syncthreads();
    const int buf = kt % NSTAGE;
    const signed char* sA = smem + buf*STAGE_B;
    const signed char* sB = sA + BM*LDT;

    #pragma unroll
    for(int ks=0; ks<2; ks++){
      const int kk = ks*32;
      uint32_t afr[4][4], bfr[4][2];
      #pragma unroll
      for(int mi=0; mi<4; mi++){
        const signed char* base = &sA[(wm + mi*16 + g)*LDT + kk + 4*q];
        afr[mi][0] = *(const uint32_t*)(base);
        afr[mi][1] = *(const uint32_t*)(base + 8*LDT);
        afr[mi][2] = *(const uint32_t*)(base + 16);
        afr[mi][3] = *(const uint32_t*)(base + 8*LDT + 16);
      }
      #pragma unroll
      for(int ni=0; ni<4; ni++){
        const signed char* base = &sB[(wn + ni*8 + g)*LDT + kk + 4*q];
        bfr[ni][0] = *(const uint32_t*)(base);
        bfr[ni][1] = *(const uint32_t*)(base + 16);
      }
      #pragma unroll
      for(int mi=0; mi<4; mi++)
        #pragma unroll
        for(int ni=0; ni<4; ni++)
          imma16832(acc[mi][ni], afr[mi], bfr[ni]);
    }
    __syncthreads();
    if(kt + NSTAGE < NKT) loads(buf, kt + NSTAGE);
    else cp_commit();       // keep group count uniform for cp_wait
  }

  // epilogue
  #pragma unroll
  for(int mi=0; mi<4; mi++){
    int r0 = bm + wm + mi*16 + g;
    int r1 = r0 + 8;
    float sc0 = rowscale[r0]*wdeq;
    float sc1 = rowscale[r1]*wdeq;
    #pragma unroll
    for(int ni=0; ni<4; ni++){
      int col = bn + wn + ni*8 + 2*q;
      float x0 = (float)acc[mi][ni][0]*sc0, x1 = (float)acc[mi][ni][1]*sc0;
      float x2 = (float)acc[mi][ni][2]*sc1, x3 = (float)acc[mi][ni][3]*sc1;
      if(MODE == 0){
        x0 = (x0>0.f)? x0*x0 : 0.f;  x1 = (x1>0.f)? x1*x1 : 0.f;
        x2 = (x2>0.f)? x2*x2 : 0.f;  x3 = (x3>0.f)? x3*x3 : 0.f;
      } else if(MODE == 1){
        x0 = 1.f/(1.f+expf(-x0)); x1 = 1.f/(1.f+expf(-x1));
        x2 = 1.f/(1.f+expf(-x2)); x3 = 1.f/(1.f+expf(-x3));
      } else {
        float2 m0 = *(const float2*)&g_rbuf[(size_t)r0*Ndim + col];
        float2 m1 = *(const float2*)&g_rbuf[(size_t)r1*Ndim + col];
        x0 *= m0.x; x1 *= m0.y; x2 *= m1.x; x3 *= m1.y;
      }
      *(float2*)&C[(size_t)r0*Ndim + col] = make_float2(x0, x1);
      *(float2*)&C[(size_t)r1*Ndim + col] = make_float2(x2, x3);
    }
  }
}

// ---------------- launch ----------------
extern "C" void kernel_launch(void* const* d_in, const int* in_sizes, int n_in,
                              void* d_out, int out_size){
  const float* hidden = (const float*)d_in[0];
  const float* tmk    = (const float*)d_in[1];
  const float* tmr    = (const float*)d_in[2];
  const float* w_key  = (const float*)d_in[3];
  const float* w_rec  = (const float*)d_in[4];
  const float* w_val  = (const float*)d_in[5];
  const float* nk     = (const float*)d_in[6];
  const float* nr     = (const float*)d_in[7];
  const float* nv     = (const float*)d_in[8];
  float* out = (float*)d_out;

  signed char *wkq, *wrq, *wvq;
  cudaGetSymbolAddress((void**)&wkq, g_wkq);
  cudaGetSymbolAddress((void**)&wrq, g_wrq);
  cudaGetSymbolAddress((void**)&wvq, g_wvq);

  const int SMEM_TOTAL = NSTAGE*STAGE_B;   // 61440
  cudaFuncSetAttribute(k_gemm<0>, cudaFuncAttributeMaxDynamicSharedMemorySize, SMEM_TOTAL);
  cudaFuncSetAttribute(k_gemm<1>, cudaFuncAttributeMaxDynamicSharedMemorySize, SMEM_TOTAL);
  cudaFuncSetAttribute(k_gemm<2>, cudaFuncAttributeMaxDynamicSharedMemorySize, SMEM_TOTAL);

  // 1) weight scales
  k_absum<<<1024,256>>>(w_key, (F_*H_)/4, 0);
  k_absum<<<1024,256>>>(w_rec, (H_*H_)/4, 1024);
  k_absum<<<1024,256>>>(w_val, (H_*F_)/4, 2048);
  k_wsfin<<<1,1024>>>();

  // 2) ternary weight codes (int8)
  k_quantw<<<4096,256>>>(w_key, wkq, (F_*H_)/4, 0);
  k_quantw<<<1024,256>>>(w_rec, wrq, (H_*H_)/4, 1);
  k_quantw<<<4096,256>>>(w_val, wvq, (H_*F_)/4, 2);

  // 3) token-shift mix + RMSNorm + int8 codes for key_in / rec_in
  k_actprep<<<M_,256>>>(hidden, tmk, tmr, nk, nr);

  // 4) key GEMM -> relu^2 -> k (fp32)
  k_gemm<0><<<dim3(F_/BN, M_/BM), 256, NSTAGE*STAGE_B>>>(nullptr);

  // 5) RMSNorm + int8 codes for k
  k_quantK<<<M_,256>>>(nv);

  // 6) receptance GEMM -> sigmoid -> r
  k_gemm<1><<<dim3(H_/BN, M_/BM), 256, NSTAGE*STAGE_B>>>(nullptr);

  // 7) value GEMM -> * r -> out
  k_gemm<2><<<dim3(H_/BN, M_/BM), 256, NSTAGE*STAGE_B>>>(out);
}

// round 5
// speedup vs baseline: 2.2300x; 2.2300x over previous
#include <cuda_runtime.h>
#include <cuda_bf16.h>
#include <cstdint>

#define B_ 4
#define T_ 2048
#define H_ 2048
#define F_ 8192
#define M_ (B_*T_)   // 8192 tokens

// ---------------- device scratch (static; no allocations) ----------------
__device__ __nv_bfloat16 g_wkq[(size_t)F_*H_];   // ternary key weight codes
__device__ __nv_bfloat16 g_wrq[(size_t)H_*H_];   // ternary receptance weight codes
__device__ __nv_bfloat16 g_wvq[(size_t)H_*F_];   // ternary value weight codes
__device__ __nv_bfloat16 g_aK[(size_t)M_*H_];    // int8 codes of key_in (as bf16)
__device__ __nv_bfloat16 g_aR[(size_t)M_*H_];    // int8 codes of rec_in
__device__ __nv_bfloat16 g_aV[(size_t)M_*F_];    // int8 codes of k
__device__ float g_kraw[(size_t)M_*F_];          // k = relu(.)^2, fp32
__device__ float g_rbuf[(size_t)M_*H_];          // sigmoid(receptance)
__device__ float g_sK[M_], g_sR[M_], g_sV[M_];   // per-row dequant scale
__device__ float g_part[3*1024];
__device__ float g_ws[6];                        // [2i]=ws, [2i+1]=1/ws

// ---------------- reductions ----------------
__device__ __forceinline__ float warpSum(float v){
  #pragma unroll
  for(int o=16;o;o>>=1) v += __shfl_xor_sync(0xffffffffu, v, o);
  return v;
}
__device__ __forceinline__ float warpMax(float v){
  #pragma unroll
  for(int o=16;o;o>>=1) v = fmaxf(v, __shfl_xor_sync(0xffffffffu, v, o));
  return v;
}
__device__ __forceinline__ float blkSum(float v, float* sm){
  int t = threadIdx.x, nw = blockDim.x >> 5;
  v = warpSum(v);
  if((t&31)==0) sm[t>>5] = v;
  __syncthreads();
  float r = (t < nw) ? sm[t] : 0.f;
  r = warpSum(r);
  if(t==0) sm[0] = r;
  __syncthreads();
  r = sm[0];
  __syncthreads();
  return r;
}
__device__ __forceinline__ float blkMax(float v, float* sm){
  int t = threadIdx.x, nw = blockDim.x >> 5;
  v = warpMax(v);
  if((t&31)==0) sm[t>>5] = v;
  __syncthreads();
  float r = (t < nw) ? sm[t] : 0.f;
  r = warpMax(r);
  if(t==0) sm[0] = r;
  __syncthreads();
  r = sm[0];
  __syncthreads();
  return r;
}

// ---------------- weight scale: two-stage deterministic mean(|w|) ----------------
__global__ void k_absum(const float* __restrict__ w, int n4, int poff){
  __shared__ float sm[32];
  float s = 0.f;
  const float4* w4 = (const float4*)w;
  for(int i = blockIdx.x*blockDim.x + threadIdx.x; i < n4; i += gridDim.x*blockDim.x){
    float4 v = w4[i];
    s += fabsf(v.x) + fabsf(v.y) + fabsf(v.z) + fabsf(v.w);
  }
  s = blkSum(s, sm);
  if(threadIdx.x == 0) g_part[poff + blockIdx.x] = s;
}

__global__ void k_wsfin(){
  __shared__ float sm[32];
  const float cnts[3] = {(float)((size_t)F_*H_), (float)((size_t)H_*H_), (float)((size_t)H_*F_)};
  for(int i=0;i<3;i++){
    float v = g_part[i*1024 + threadIdx.x];
    float tot = blkSum(v, sm);
    if(threadIdx.x == 0){
      float mean = tot / cnts[i];
      float c = fmaxf(mean, 1e-5f);
      g_ws[2*i]   = 1.f/c;
      g_ws[2*i+1] = c;
    }
    __syncthreads();
  }
}

// ---------------- ternary weight quantization ----------------
__global__ void k_quantw(const float* __restrict__ w, __nv_bfloat16* __restrict__ wq,
                         int n4, int wsidx){
  float ws = g_ws[2*wsidx];
  for(int i = blockIdx.x*blockDim.x + threadIdx.x; i < n4; i += gridDim.x*blockDim.x){
    float4 v = ((const float4*)w)[i];
    float q0 = fminf(fmaxf(rintf(v.x*ws), -1.f), 1.f);
    float q1 = fminf(fmaxf(rintf(v.y*ws), -1.f), 1.f);
    float q2 = fminf(fmaxf(rintf(v.z*ws), -1.f), 1.f);
    float q3 = fminf(fmaxf(rintf(v.w*ws), -1.f), 1.f);
    __nv_bfloat162* o = ((__nv_bfloat162*)wq) + 2*(size_t)i;
    o[0] = __floats2bfloat162_rn(q0, q1);
    o[1] = __floats2bfloat162_rn(q2, q3);
  }
}

// ---------------- token shift + RMSNorm + int8 activation quant ----------------
__global__ void k_actprep(const float* __restrict__ hidden,
                          const float* __restrict__ tmk, const float* __restrict__ tmr,
                          const float* __restrict__ nk,  const float* __restrict__ nr){
  __shared__ float sm[32];
  int m = blockIdx.x;
  int t = m & (T_-1);
  const float* cur = hidden + (size_t)m*H_;
  float kin[8], rin[8];
  float ssk=0.f, ssr=0.f, amk=0.f, amr=0.f;
  #pragma unroll
  for(int j=0;j<8;j++){
    int h = threadIdx.x + j*256;
    float xc = cur[h];
    float xp = (t==0) ? 0.f : cur[h - H_];
    float a = tmk[h], b = tmr[h];
    float ki = xc*a + xp*(1.f-a);
    float ri = xc*b + xp*(1.f-b);
    kin[j]=ki; rin[j]=ri;
    ssk += ki*ki; ssr += ri*ri;
    amk = fmaxf(amk, fabsf(ki*nk[h]));
    amr = fmaxf(amr, fabsf(ri*nr[h]));
  }
  float tssk = blkSum(ssk, sm);
  float tssr = blkSum(ssr, sm);
  float tamk = blkMax(amk, sm);
  float tamr = blkMax(amr, sm);
  float rk = rsqrtf(tssk*(1.f/H_) + 1e-8f);
  float rr = rsqrtf(tssr*(1.f/H_) + 1e-8f);
  float rsK = fmaxf(tamk*rk, 1e-5f);
  float rsR = fmaxf(tamr*rr, 1e-5f);
  float sk = 127.f/rsK, sr = 127.f/rsR;
  #pragma unroll
  for(int j=0;j<8;j++){
    int h = threadIdx.x + j*256;
    float qk = fminf(fmaxf(rintf(kin[j]*nk[h]*rk*sk), -128.f), 127.f);
    float qr = fminf(fmaxf(rintf(rin[j]*nr[h]*rr*sr), -128.f), 127.f);
    g_aK[(size_t)m*H_ + h] = __float2bfloat16(qk);
    g_aR[(size_t)m*H_ + h] = __float2bfloat16(qr);
  }
  if(threadIdx.x == 0){ g_sK[m] = rsK*(1.f/127.f); g_sR[m] = rsR*(1.f/127.f); }
}

// ---------------- RMSNorm + int8 quant of k rows (F=8192) ----------------
__global__ void k_quantK(const float* __restrict__ nv){
  __shared__ float sm[32];
  int m = blockIdx.x;
  const float* row = g_kraw + (size_t)m*F_;
  float v[32];
  float ss=0.f, am=0.f;
  #pragma unroll
  for(int j=0;j<32;j++){
    int h = threadIdx.x + j*256;
    float x = row[h];
    v[j] = x;
    ss += x*x;
    am = fmaxf(am, fabsf(x*nv[h]));
  }
  float tss = blkSum(ss, sm);
  float tam = blkMax(am, sm);
  float rinv = rsqrtf(tss*(1.f/F_) + 1e-8f);
  float rs = fmaxf(tam*rinv, 1e-5f);
  float s = 127.f/rs;
  #pragma unroll
  for(int j=0;j<32;j++){
    int h = threadIdx.x + j*256;
    float q = fminf(fmaxf(rintf(v[j]*nv[h]*rinv*s), -128.f), 127.f);
    g_aV[(size_t)m*F_ + h] = __float2bfloat16(q);
  }
  if(threadIdx.x == 0) g_sV[m] = rs*(1.f/127.f);
}

// ---------------- bf16 tensor-core GEMM: C[M,N] = A[M,K] * Bw[N,K]^T ----------------
#define BM 128
#define BN 128
#define BKg 64          // 64 bf16 elems = 128 B per row
#define LDT 72          // elems: 64 + 8 pad -> 144B row stride, conflict-free frag LDS
#define NSTAGE 3
#define STAGE_E ((BM+BN)*LDT)           // elems per stage: 18432
#define STAGE_BYTES (STAGE_E*2)         // 36864 B
#define SMEM_TOTAL (NSTAGE*STAGE_BYTES) // 110592 B

__device__ __forceinline__ void cp16(uint32_t s, const void* g){
  asm volatile("cp.async.cg.shared.global [%0], [%1], 16;" :: "r"(s), "l"(g));
}
__device__ __forceinline__ void cp_commit(){ asm volatile("cp.async.commit_group;" ::: "memory"); }
template<int N> __device__ __forceinline__ void cp_wait(){
  asm volatile("cp.async.wait_group %0;" :: "n"(N) : "memory");
}
__device__ __forceinline__ void mma16816(float* c, const uint32_t* a, const uint32_t* b){
  asm volatile(
    "mma.sync.aligned.m16n8k16.row.col.f32.bf16.bf16.f32 "
    "{%0,%1,%2,%3}, {%4,%5,%6,%7}, {%8,%9}, {%0,%1,%2,%3};\n"
    : "+f"(c[0]), "+f"(c[1]), "+f"(c[2]), "+f"(c[3])
    : "r"(a[0]), "r"(a[1]), "r"(a[2]), "r"(a[3]), "r"(b[0]), "r"(b[1]));
}

// MODE 0: key   -> g_kraw = relu(x)^2
// MODE 1: rec   -> g_rbuf = sigmoid(x)
// MODE 2: value -> Cout   = x * g_rbuf
template<int MODE>
__global__ __launch_bounds__(256,2) void k_gemm(float* __restrict__ Cout){
  constexpr int Ndim = (MODE==0) ? F_ : H_;
  constexpr int Kdim = (MODE==2) ? F_ : H_;
  constexpr int NKT  = Kdim / BKg;

  const __nv_bfloat16* __restrict__ A  = (MODE==0) ? g_aK  : (MODE==1) ? g_aR  : g_aV;
  const __nv_bfloat16* __restrict__ Bw = (MODE==0) ? g_wkq : (MODE==1) ? g_wrq : g_wvq;
  const float* __restrict__ rowscale   = (MODE==0) ? g_sK  : (MODE==1) ? g_sR  : g_sV;
  float* __restrict__ C                = (MODE==0) ? g_kraw : (MODE==1) ? g_rbuf : Cout;
  const float wdeq = g_ws[2*((MODE==0)?0:(MODE==1)?1:2) + 1];

  extern __shared__ __align__(128) __nv_bfloat16 smem[];

  const int tid = threadIdx.x;
  const int bm = blockIdx.y*BM, bn = blockIdx.x*BN;

  auto loads = [&](int buf, int kt){
    __nv_bfloat16* st = smem + buf*STAGE_E;
    const __nv_bfloat16* Ak = A  + (size_t)bm*Kdim + kt*BKg;
    const __nv_bfloat16* Bk = Bw + (size_t)bn*Kdim + kt*BKg;
    #pragma unroll
    for(int i=0;i<8;i++){
      int chunk = tid + 256*i;         // 0..2047 : 256 rows x 8 x 16B
      int row = chunk >> 3;
      int kc  = (chunk & 7) << 3;      // elems: 0,8,...,56
      const __nv_bfloat16* gp = (row < BM) ? (Ak + (size_t)row*Kdim + kc)
                                           : (Bk + (size_t)(row-BM)*Kdim + kc);
      cp16((uint32_t)__cvta_generic_to_shared(st + row*LDT + kc), gp);
    }
    cp_commit();
  };

  const int warp = tid >> 5, lane = tid & 31;
  const int wm = (warp >> 2) * 64;   // 2 warps in M
  const int wn = (warp & 3) * 32;    // 4 warps in N
  const int g = lane >> 2, q = lane & 3;

  float acc[4][4][4];
  #pragma unroll
  for(int a0=0;a0<4;a0++)
    #pragma unroll
    for(int b0=0;b0<4;b0++)
      #pragma unroll
      for(int c0=0;c0<4;c0++) acc[a0][b0][c0]=0.f;

  #pragma unroll
  for(int s=0;s<NSTAGE;s++) loads(s, s);

  #pragma unroll 1
  for(int kt=0; kt<NKT; kt++){
    cp_wait<NSTAGE-1>();
    __syncthreads();
    const int buf = kt % NSTAGE;
    const __nv_bfloat16* sA = smem + buf*STAGE_E;
    const __nv_bfloat16* sB = sA + BM*LDT;

    #pragma unroll
    for(int ks=0; ks<4; ks++){
      const int kk = ks*16;
      uint32_t afr[4][4], bfr[4][2];
      #pragma unroll
      for(int mi=0; mi<4; mi++){
        const __nv_bfloat16* base = &sA[(wm + mi*16 + g)*LDT + kk + 2*q];
        afr[mi][0] = *(const uint32_t*)(base);
        afr[mi][1] = *(const uint32_t*)(base + 8*LDT);
        afr[mi][2] = *(const uint32_t*)(base + 8);
        afr[mi][3] = *(const uint32_t*)(base + 8*LDT + 8);
      }
      #pragma unroll
      for(int ni=0; ni<4; ni++){
        const __nv_bfloat16* base = &sB[(wn + ni*8 + g)*LDT + kk + 2*q];
        bfr[ni][0] = *(const uint32_t*)(base);
        bfr[ni][1] = *(const uint32_t*)(base + 8);
      }
      #pragma unroll
      for(int mi=0; mi<4; mi++)
        #pragma unroll
        for(int ni=0; ni<4; ni++)
          mma16816(acc[mi][ni], afr[mi], bfr[ni]);
    }
    __syncthreads();
    if(kt + NSTAGE < NKT) loads(buf, kt + NSTAGE);
    else cp_commit();       // keep group count uniform for cp_wait
  }

  // epilogue
  #pragma unroll
  for(int mi=0; mi<4; mi++){
    int r0 = bm + wm + mi*16 + g;
    int r1 = r0 + 8;
    float sc0 = rowscale[r0]*wdeq;
    float sc1 = rowscale[r1]*wdeq;
    #pragma unroll
    for(int ni=0; ni<4; ni++){
      int col = bn + wn + ni*8 + 2*q;
      float x0 = acc[mi][ni][0]*sc0, x1 = acc[mi][ni][1]*sc0;
      float x2 = acc[mi][ni][2]*sc1, x3 = acc[mi][ni][3]*sc1;
      if(MODE == 0){
        x0 = (x0>0.f)? x0*x0 : 0.f;  x1 = (x1>0.f)? x1*x1 : 0.f;
        x2 = (x2>0.f)? x2*x2 : 0.f;  x3 = (x3>0.f)? x3*x3 : 0.f;
      } else if(MODE == 1){
        x0 = 1.f/(1.f+expf(-x0)); x1 = 1.f/(1.f+expf(-x1));
        x2 = 1.f/(1.f+expf(-x2)); x3 = 1.f/(1.f+expf(-x3));
      } else {
        float2 m0 = *(const float2*)&g_rbuf[(size_t)r0*Ndim + col];
        float2 m1 = *(const float2*)&g_rbuf[(size_t)r1*Ndim + col];
        x0 *= m0.x; x1 *= m0.y; x2 *= m1.x; x3 *= m1.y;
      }
      *(float2*)&C[(size_t)r0*Ndim + col] = make_float2(x0, x1);
      *(float2*)&C[(size_t)r1*Ndim + col] = make_float2(x2, x3);
    }
  }
}

// ---------------- launch ----------------
extern "C" void kernel_launch(void* const* d_in, const int* in_sizes, int n_in,
                              void* d_out, int out_size){
  const float* hidden = (const float*)d_in[0];
  const float* tmk    = (const float*)d_in[1];
  const float* tmr    = (const float*)d_in[2];
  const float* w_key  = (const float*)d_in[3];
  const float* w_rec  = (const float*)d_in[4];
  const float* w_val  = (const float*)d_in[5];
  const float* nk     = (const float*)d_in[6];
  const float* nr     = (const float*)d_in[7];
  const float* nv     = (const float*)d_in[8];
  float* out = (float*)d_out;

  __nv_bfloat16 *wkq, *wrq, *wvq;
  cudaGetSymbolAddress((void**)&wkq, g_wkq);
  cudaGetSymbolAddress((void**)&wrq, g_wrq);
  cudaGetSymbolAddress((void**)&wvq, g_wvq);

  cudaFuncSetAttribute(k_gemm<0>, cudaFuncAttributeMaxDynamicSharedMemorySize, SMEM_TOTAL);
  cudaFuncSetAttribute(k_gemm<1>, cudaFuncAttributeMaxDynamicSharedMemorySize, SMEM_TOTAL);
  cudaFuncSetAttribute(k_gemm<2>, cudaFuncAttributeMaxDynamicSharedMemorySize, SMEM_TOTAL);

  // 1) weight scales
  k_absum<<<1024,256>>>(w_key, (F_*H_)/4, 0);
  k_absum<<<1024,256>>>(w_rec, (H_*H_)/4, 1024);
  k_absum<<<1024,256>>>(w_val, (H_*F_)/4, 2048);
  k_wsfin<<<1,1024>>>();

  // 2) ternary weight codes
  k_quantw<<<4096,256>>>(w_key, wkq, (F_*H_)/4, 0);
  k_quantw<<<1024,256>>>(w_rec, wrq, (H_*H_)/4, 1);
  k_quantw<<<4096,256>>>(w_val, wvq, (H_*F_)/4, 2);

  // 3) token-shift mix + RMSNorm + int8 codes for key_in / rec_in
  k_actprep<<<M_,256>>>(hidden, tmk, tmr, nk, nr);

  // 4) key GEMM -> relu^2 -> k (fp32)
  k_gemm<0><<<dim3(F_/BN, M_/BM), 256, SMEM_TOTAL>>>(nullptr);

  // 5) RMSNorm + int8 codes for k
  k_quantK<<<M_,256>>>(nv);

  // 6) receptance GEMM -> sigmoid -> r
  k_gemm<1><<<dim3(H_/BN, M_/BM), 256, SMEM_TOTAL>>>(nullptr);

  // 7) value GEMM -> * r -> out
  k_gemm<2><<<dim3(H_/BN, M_/BM), 256, SMEM_TOTAL>>>(out);
}